// round 7
// baseline (speedup 1.0000x reference)
#include <cuda_runtime.h>
#include <cuda_bf16.h>
#include <math.h>
#include <stdint.h>

#define BSZ 32
#define SEQL 2048
#define INF 512
#define HID 256
#define MTOT (BSZ * SEQL)           // 65536 rows
#define XXN (BSZ * SEQL * 2 * HID)  // 33554432
#define HOUTN (4 * BSZ * HID)       // 32768

// ---------------- scratch (static device globals; no allocation) -------------
__device__ __nv_bfloat16 g_xhi [MTOT * INF];
__device__ __nv_bfloat16 g_xlo [MTOT * INF];
__device__ __nv_bfloat16 g_Wfc3[HID * 3 * INF];       // [Whi|Whi|Wlo] along k'
__device__ __nv_bfloat16 g_W23 [2 * HID * 3 * HID];
__device__ __nv_bfloat16 g_Hhi [MTOT * HID];
__device__ __nv_bfloat16 g_Hlo [MTOT * HID];
__device__ __nv_bfloat16 g_Ylhi[MTOT * HID];
__device__ __nv_bfloat16 g_Yllo[MTOT * HID];
__device__ __nv_bfloat16 g_Yrhi[MTOT * HID];
__device__ __nv_bfloat16 g_Yrlo[MTOT * HID];
__device__ float2        g_AC1 [MTOT * HID];          // packed (a, c) per element
__device__ float2        g_AC2a[MTOT * HID];
__device__ float2        g_AC2b[MTOT * HID];
__device__ float         g_hdump[4 * BSZ * HID];

#define K2LOG2E 2.8853900817779268f   // 2*log2(e)

// ---------------- fast math ----------------
__device__ __forceinline__ float fast_ex2(float x) {
    float y; asm("ex2.approx.f32 %0, %1;" : "=f"(y) : "f"(x)); return y;
}
__device__ __forceinline__ float fast_rcp(float x) {
    float y; asm("rcp.approx.f32 %0, %1;" : "=f"(y) : "f"(x)); return y;
}
__device__ __forceinline__ float fast_sigmoid(float z) {
    return fast_rcp(1.0f + fast_ex2(-1.4426950408889634f * z));
}
__device__ __forceinline__ void split_bf16(float v, __nv_bfloat16& hi, __nv_bfloat16& lo) {
    hi = __float2bfloat16(v);
    lo = __float2bfloat16(v - __bfloat162float(hi));
}

// ---------------- PTX helpers ----------------
__device__ __forceinline__ void ldsm4(uint32_t (&r)[4], uint32_t saddr) {
    asm volatile("ldmatrix.sync.aligned.m8n8.x4.shared.b16 {%0,%1,%2,%3}, [%4];"
                 : "=r"(r[0]), "=r"(r[1]), "=r"(r[2]), "=r"(r[3]) : "r"(saddr));
}
__device__ __forceinline__ void mma16816(float (&d)[4], const uint32_t (&a)[4],
                                         uint32_t b0, uint32_t b1) {
    asm volatile("mma.sync.aligned.m16n8k16.row.col.f32.bf16.bf16.f32 "
                 "{%0,%1,%2,%3}, {%4,%5,%6,%7}, {%8,%9}, {%0,%1,%2,%3};"
                 : "+f"(d[0]), "+f"(d[1]), "+f"(d[2]), "+f"(d[3])
                 : "r"(a[0]), "r"(a[1]), "r"(a[2]), "r"(a[3]), "r"(b0), "r"(b1));
}
__device__ __forceinline__ void cpa16(uint32_t s, const void* g) {
    asm volatile("cp.async.cg.shared.global [%0], [%1], 16;" :: "r"(s), "l"(g));
}
__device__ __forceinline__ void cpa_commit() { asm volatile("cp.async.commit_group;"); }

// ---------------- conversion kernels ----------------
__global__ void convert_x_kernel(const float* __restrict__ x,
                                 __nv_bfloat16* __restrict__ xhi,
                                 __nv_bfloat16* __restrict__ xlo, int n4)
{
    int i = blockIdx.x * blockDim.x + threadIdx.x;
    if (i >= n4) return;
    float4 v = reinterpret_cast<const float4*>(x)[i];
    __nv_bfloat16 h0, l0, h1, l1, h2, l2, h3, l3;
    split_bf16(v.x, h0, l0); split_bf16(v.y, h1, l1);
    split_bf16(v.z, h2, l2); split_bf16(v.w, h3, l3);
    reinterpret_cast<__nv_bfloat162*>(xhi)[2 * i]     = __nv_bfloat162(h0, h1);
    reinterpret_cast<__nv_bfloat162*>(xhi)[2 * i + 1] = __nv_bfloat162(h2, h3);
    reinterpret_cast<__nv_bfloat162*>(xlo)[2 * i]     = __nv_bfloat162(l0, l1);
    reinterpret_cast<__nv_bfloat162*>(xlo)[2 * i + 1] = __nv_bfloat162(l2, l3);
}

// Build W' = [Whi | Whi | Wlo] (k' = 3K) for W_fc and both W2 layers.
__global__ void convert_w_kernel(const float* __restrict__ Wfc,
                                 const float* __restrict__ W2,
                                 __nv_bfloat16* __restrict__ Wfc3,
                                 __nv_bfloat16* __restrict__ W23)
{
    int i = blockIdx.x * blockDim.x + threadIdx.x;
    const int t1 = HID * INF;
    const int t2 = 2 * HID * HID;
    if (i < t1) {
        int n = i / INF, k = i % INF;
        __nv_bfloat16 hi, lo; split_bf16(Wfc[i], hi, lo);
        __nv_bfloat16* base = Wfc3 + (size_t)n * (3 * INF);
        base[k] = hi; base[INF + k] = hi; base[2 * INF + k] = lo;
    } else if (i < t1 + t2) {
        int j = i - t1;
        int l = j / (HID * HID); int r = j % (HID * HID);
        int n = r / HID, k = r % HID;
        __nv_bfloat16 hi, lo; split_bf16(W2[j], hi, lo);
        __nv_bfloat16* base = W23 + (size_t)l * HID * (3 * HID) + (size_t)n * (3 * HID);
        base[k] = hi; base[HID + k] = hi; base[2 * HID + k] = lo;
    }
}

// ---------------- tensor-core GEMM -------------------------------------------
// Block tile 128x64, 8 warps (32x32 each), k-chunk 32, 3-stage cp.async
// circular pipeline, ONE __syncthreads per chunk.
// OUT=0: C = A@W'^T + bias -> split bf16 planes Chi/Clo.
// OUT=1: gate epilogue: g = sigmoid(acc+bias); reload x = Ahi+Alo at (m,n);
//        emit packed scan coefficients AC[m,n] = (2log2e*x*g, 2log2e*x^2*(1-g)).
// blockIdx.z == 1 selects the second (A2 -> ACb) problem (fused layer-2 gates).
#define A_STRIDE 40
#define A_TILE (128 * A_STRIDE)
#define W_TILE (64 * A_STRIDE)
#define NSTG 3

template <int OUT>
__global__ __launch_bounds__(256, 2)
void gemm_tc(const __nv_bfloat16* __restrict__ Ahi_, const __nv_bfloat16* __restrict__ Alo_,
             const __nv_bfloat16* __restrict__ Ahi2, const __nv_bfloat16* __restrict__ Alo2,
             const __nv_bfloat16* __restrict__ W3, const float* __restrict__ bias,
             float2* __restrict__ ACa, float2* __restrict__ ACb,
             __nv_bfloat16* __restrict__ Chi, __nv_bfloat16* __restrict__ Clo, int K)
{
    __shared__ __nv_bfloat16 As[NSTG][A_TILE];
    __shared__ __nv_bfloat16 Ws[NSTG][W_TILE];

    const __nv_bfloat16* Ahi = (blockIdx.z == 0) ? Ahi_ : Ahi2;
    const __nv_bfloat16* Alo = (blockIdx.z == 0) ? Alo_ : Alo2;
    float2* AC = (blockIdx.z == 0) ? ACa : ACb;

    const int tid  = threadIdx.x;
    const int bm   = blockIdx.x * 128;
    const int bn   = blockIdx.y * 64;
    const int warp = tid >> 5;
    const int lane = tid & 31;
    const int K3   = 3 * K;
    const int n1   = K >> 5;
    const int nc   = 3 * n1;

    const uint32_t sA = (uint32_t)__cvta_generic_to_shared(&As[0][0]);
    const uint32_t sW = (uint32_t)__cvta_generic_to_shared(&Ws[0][0]);

    const int ar0 = tid >> 2, ar1 = (tid + 256) >> 2;
    const int ac  = (tid & 3) * 8;
    const int wr  = tid >> 2;
    const uint32_t sAoff0 = (uint32_t)(ar0 * A_STRIDE + ac) * 2;
    const uint32_t sAoff1 = (uint32_t)(ar1 * A_STRIDE + ac) * 2;
    const uint32_t sWoff  = (uint32_t)(wr  * A_STRIDE + ac) * 2;
    const __nv_bfloat16* Wg = W3 + (size_t)(bn + wr) * K3 + ac;

    float acc[2][4][4];
#pragma unroll
    for (int a = 0; a < 2; a++)
#pragma unroll
        for (int b = 0; b < 4; b++)
#pragma unroll
            for (int c = 0; c < 4; c++) acc[a][b][c] = 0.0f;

    auto prefetch = [&](int c, int buf) {
        const __nv_bfloat16* Aseg; int kk;
        if (c < n1)           { Aseg = Ahi; kk = c; }
        else if (c < 2 * n1)  { Aseg = Alo; kk = c - n1; }
        else                  { Aseg = Ahi; kk = c - 2 * n1; }
        const __nv_bfloat16* Abase = Aseg + (size_t)bm * K + kk * 32 + ac;
        cpa16(sA + buf * (A_TILE * 2) + sAoff0, Abase + (size_t)ar0 * K);
        cpa16(sA + buf * (A_TILE * 2) + sAoff1, Abase + (size_t)ar1 * K);
        cpa16(sW + buf * (W_TILE * 2) + sWoff,  Wg + c * 32);
    };

    // prologue: 2 stages in flight
    prefetch(0, 0); cpa_commit();
    prefetch(1, 1); cpa_commit();
    asm volatile("cp.async.wait_group 1;");
    __syncthreads();

    const int wm = warp & 3;
    const int wn = warp >> 2;
    const int aRow = wm * 32 + (lane & 15);
    const int aColB = (lane >> 4) * 8;
    const int bRow = wn * 32 + (lane & 7) + ((lane >> 4) & 1) * 8;
    const int bColB = ((lane >> 3) & 1) * 8;

    int buf = 0;
    for (int c = 0; c < nc; c++) {
        const uint32_t aBase = sA + buf * (A_TILE * 2);
        const uint32_t wBase = sW + buf * (W_TILE * 2);
#pragma unroll
        for (int ks = 0; ks < 2; ks++) {
            uint32_t afr[2][4], bfr[2][4];
#pragma unroll
            for (int mi = 0; mi < 2; mi++)
                ldsm4(afr[mi], aBase + (uint32_t)((aRow + mi * 16) * A_STRIDE
                                                  + ks * 16 + aColB) * 2);
#pragma unroll
            for (int bi = 0; bi < 2; bi++)
                ldsm4(bfr[bi], wBase + (uint32_t)((bRow + bi * 16) * A_STRIDE
                                                  + ks * 16 + bColB) * 2);
#pragma unroll
            for (int mi = 0; mi < 2; mi++) {
                mma16816(acc[mi][0], afr[mi], bfr[0][0], bfr[0][1]);
                mma16816(acc[mi][1], afr[mi], bfr[0][2], bfr[0][3]);
                mma16816(acc[mi][2], afr[mi], bfr[1][0], bfr[1][1]);
                mma16816(acc[mi][3], afr[mi], bfr[1][2], bfr[1][3]);
            }
        }
        if (c + 2 < nc) {
            int pf = buf + 2; if (pf >= NSTG) pf -= NSTG;
            prefetch(c + 2, pf);
            cpa_commit();
            asm volatile("cp.async.wait_group 1;");
        } else {
            asm volatile("cp.async.wait_group 0;");
        }
        __syncthreads();
        buf = (buf + 1 == NSTG) ? 0 : buf + 1;
    }

    // epilogue
#pragma unroll
    for (int mi = 0; mi < 2; mi++) {
#pragma unroll
        for (int ni = 0; ni < 4; ni++) {
            const int m0 = bm + wm * 32 + mi * 16 + (lane >> 2);
            const int n0 = bn + wn * 32 + ni * 8 + (lane & 3) * 2;
            const float b0 = bias[n0], b1 = bias[n0 + 1];
            float v00 = acc[mi][ni][0] + b0, v01 = acc[mi][ni][1] + b1;
            float v10 = acc[mi][ni][2] + b0, v11 = acc[mi][ni][3] + b1;
            if (OUT == 1) {
                // gate + scan-coefficient fusion (K == HID here)
#pragma unroll
                for (int r = 0; r < 2; r++) {
                    const int m = m0 + r * 8;
                    const float ga = fast_sigmoid(r ? v10 : v00);
                    const float gb = fast_sigmoid(r ? v11 : v01);
                    __nv_bfloat162 hh = *reinterpret_cast<const __nv_bfloat162*>(
                        Ahi + (size_t)m * HID + n0);
                    __nv_bfloat162 ll = *reinterpret_cast<const __nv_bfloat162*>(
                        Alo + (size_t)m * HID + n0);
                    const float xa = __bfloat162float(hh.x) + __bfloat162float(ll.x);
                    const float xb = __bfloat162float(hh.y) + __bfloat162float(ll.y);
                    float4 o;
                    o.x = K2LOG2E * xa * ga;
                    o.y = K2LOG2E * xa * xa * (1.0f - ga);
                    o.z = K2LOG2E * xb * gb;
                    o.w = K2LOG2E * xb * xb * (1.0f - gb);
                    *reinterpret_cast<float4*>(AC + (size_t)m * HID + n0) = o;
                }
            } else {
                __nv_bfloat16 h0, l0, h1, l1;
                split_bf16(v00, h0, l0); split_bf16(v01, h1, l1);
                *reinterpret_cast<__nv_bfloat162*>(Chi + (size_t)m0 * HID + n0) = __nv_bfloat162(h0, h1);
                *reinterpret_cast<__nv_bfloat162*>(Clo + (size_t)m0 * HID + n0) = __nv_bfloat162(l0, l1);
                split_bf16(v10, h0, l0); split_bf16(v11, h1, l1);
                *reinterpret_cast<__nv_bfloat162*>(Chi + (size_t)(m0 + 8) * HID + n0) = __nv_bfloat162(h0, h1);
                *reinterpret_cast<__nv_bfloat162*>(Clo + (size_t)(m0 + 8) * HID + n0) = __nv_bfloat162(l0, l1);
            }
        }
    }
}

// ---------------- sequential scan ------------------------------------------
// Per step: load packed (a,c); h = tanh-chain:  v = a*h + c; t = ex2(v);
// h = 1 - 2*rcp(1+t).  Chain ~44 cyc; everything else is off-chain.
// OM=0: write split bf16 planes (layer-1 Y). OM=1: write fp32 into d_out.
#define SU 16
template <int OM>
__global__ __launch_bounds__(64)
void scan_ac(const float2* __restrict__ acF, const float2* __restrict__ acR,
             __nv_bfloat16* __restrict__ yFhi, __nv_bfloat16* __restrict__ yFlo,
             __nv_bfloat16* __restrict__ yRhi, __nv_bfloat16* __restrict__ yRlo,
             float* __restrict__ outF,
             float* __restrict__ hF, float* __restrict__ hR)
{
    const int gid = blockIdx.x * 64 + threadIdx.x;   // 0..16383
    const int dir = gid >> 13;
    const int id  = gid & 8191;
    const int b = id >> 8;
    const int j = id & 255;

    const float2* acp = dir ? acR : acF;
    __nv_bfloat16* yh = dir ? yRhi : yFhi;
    __nv_bfloat16* yl = dir ? yRlo : yFlo;
    float* hp = dir ? hR : hF;
    const int t0 = dir ? (SEQL - 1) : 0;
    const int dt = dir ? -1 : 1;

    const int base = b * SEQL * HID + j;
    const size_t obase = (size_t)b * SEQL * (2 * HID) + dir * HID + j;

    float aa[2][SU], cc[2][SU];

    auto LOAD = [&](int s0, int bufi) {
#pragma unroll
        for (int u = 0; u < SU; u++) {
            const int t = t0 + dt * (s0 + u);
            const float2 v = __ldg(acp + base + t * HID);
            aa[bufi][u] = v.x;
            cc[bufi][u] = v.y;
        }
    };

    LOAD(0, 0);
    float h = 0.0f;
    int cur = 0;
    for (int s0 = 0; s0 < SEQL; s0 += SU) {
        const bool more = (s0 + SU) < SEQL;
        if (more) LOAD(s0 + SU, cur ^ 1);
#pragma unroll
        for (int u = 0; u < SU; u++) {
            const float v = fmaf(aa[cur][u], h, cc[cur][u]);
            const float t = fast_ex2(v);
            h = fmaf(-2.0f, fast_rcp(t + 1.0f), 1.0f);
            const int tt = t0 + dt * (s0 + u);
            if (OM == 0) {
                __nv_bfloat16 hi, lo; split_bf16(h, hi, lo);
                yh[base + tt * HID] = hi;
                yl[base + tt * HID] = lo;
            } else {
                outF[obase + (size_t)tt * (2 * HID)] = h;
            }
        }
        cur ^= 1;
    }
    hp[(b << 8) + j] = h;
}

// ---------------- launch ----------------
extern "C" void kernel_launch(void* const* d_in, const int* in_sizes, int n_in,
                              void* d_out, int out_size)
{
    const float* x    = (const float*)d_in[0];  // [32,2048,512]
    const float* W_fc = (const float*)d_in[1];  // [256,512]
    const float* b_fc = (const float*)d_in[2];  // [256]
    // d_in[3] (W1), d_in[4] (b1): mathematically dead (blending1 == identity)
    const float* W2   = (const float*)d_in[5];  // [2,256,256]
    const float* b2   = (const float*)d_in[6];  // [2,256]
    float* out = (float*)d_out;

    __nv_bfloat16 *xhi, *xlo, *Wfc3, *W23, *Hhi, *Hlo, *Ylhi, *Yllo, *Yrhi, *Yrlo;
    float2 *AC1, *AC2a, *AC2b;
    float *hd;
    cudaGetSymbolAddress((void**)&xhi,  g_xhi);
    cudaGetSymbolAddress((void**)&xlo,  g_xlo);
    cudaGetSymbolAddress((void**)&Wfc3, g_Wfc3);
    cudaGetSymbolAddress((void**)&W23,  g_W23);
    cudaGetSymbolAddress((void**)&Hhi,  g_Hhi);
    cudaGetSymbolAddress((void**)&Hlo,  g_Hlo);
    cudaGetSymbolAddress((void**)&Ylhi, g_Ylhi);
    cudaGetSymbolAddress((void**)&Yllo, g_Yllo);
    cudaGetSymbolAddress((void**)&Yrhi, g_Yrhi);
    cudaGetSymbolAddress((void**)&Yrlo, g_Yrlo);
    cudaGetSymbolAddress((void**)&AC1,  g_AC1);
    cudaGetSymbolAddress((void**)&AC2a, g_AC2a);
    cudaGetSymbolAddress((void**)&AC2b, g_AC2b);
    cudaGetSymbolAddress((void**)&hd,   g_hdump);

    float* hout = (out_size >= XXN + HOUTN) ? (out + XXN) : hd;

    // 0) operand conversion (x -> hi/lo planes; W -> [Whi|Whi|Wlo])
    {
        int n4 = MTOT * INF / 4;
        convert_x_kernel<<<(n4 + 255) / 256, 256>>>(x, xhi, xlo, n4);
        int nw = HID * INF + 2 * HID * HID;
        convert_w_kernel<<<(nw + 255) / 256, 256>>>(W_fc, W2, Wfc3, W23);
    }

    const dim3 blk(256);
    const dim3 grd1(MTOT / 128, HID / 64, 1);
    const dim3 grd2(MTOT / 128, HID / 64, 2);

    // 1) input projection -> split bf16 H planes
    gemm_tc<0><<<grd1, blk>>>(xhi, xlo, nullptr, nullptr, Wfc3, b_fc,
                              nullptr, nullptr, Hhi, Hlo, INF);
    // 2) layer-1 gates + scan-coefficient fusion -> AC1 (shared by both dirs)
    gemm_tc<1><<<grd1, blk>>>(Hhi, Hlo, nullptr, nullptr, W23, b2,
                              AC1, nullptr, nullptr, nullptr, HID);
    // 3) layer-1 scans (fwd+rev in one launch) -> split Y planes + h_out[0,1]
    scan_ac<0><<<256, 64>>>(AC1, AC1, Ylhi, Yllo, Yrhi, Yrlo,
                            nullptr, hout, hout + BSZ * HID);
    // 4) layer-2 gates, both directions fused via gridDim.z
    gemm_tc<1><<<grd2, blk>>>(Ylhi, Yllo, Yrhi, Yrlo,
                              W23 + (size_t)HID * 3 * HID, b2 + HID,
                              AC2a, AC2b, nullptr, nullptr, HID);
    // 5) layer-2 scans write straight into d_out + h_out[2,3]
    scan_ac<1><<<256, 64>>>(AC2a, AC2b, nullptr, nullptr, nullptr, nullptr,
                            out, hout + 2 * BSZ * HID, hout + 3 * BSZ * HID);
}